// round 12
// baseline (speedup 1.0000x reference)
#include <cuda_runtime.h>
#include <cuda_bf16.h>
#include <cuda_fp16.h>
#include <cstdint>

// Problem constants
#define Bsz   256
#define Tsz   250
#define DIN   700
#define Hd    128
#define DOUT  20
#define KT    64            // k-tile
#define NKT   11            // 704 / 64

#define REC_CTAS 48         // 5-6 samples per CTA (one warp per sample)
#define GEMM_TILES (Tsz * 2)

// Scratch
__device__ float g_h1[Tsz * Bsz * Hd];                 // h1_all[t][b][h]
__device__ __half g_Bh[NKT * 128 * KT];                 // W1^T fp16 splits [kt][n][kk]
__device__ __half g_Bm[NKT * 128 * KT];
__device__ int    g_flag[Tsz];                          // per-timestep arrivals (2 = ready)

// ---------------------------------------------------------------------------
// Prep: fp16 two-term split of W1 -> g_B{h,m}[kt][n][kk]; zero g_flag.
// ---------------------------------------------------------------------------
__global__ void prep_kernel(const float* __restrict__ W1)
{
    int idx = blockIdx.x * blockDim.x + threadIdx.x;
    if (idx < Tsz) g_flag[idx] = 0;
    if (idx >= NKT * 128 * KT) return;
    int kt = idx / (128 * KT);
    int r  = idx - kt * (128 * KT);
    int n  = r >> 6;
    int kk = r & 63;
    int k  = kt * KT + kk;
    float w = (k < DIN) ? W1[k * Hd + n] : 0.f;
    __half h = __float2half_rn(w);
    float  rm = w - __half2float(h);
    g_Bh[idx] = h;
    g_Bm[idx] = __float2half_rn(rm);
}

// ---------------------------------------------------------------------------
// helpers
// ---------------------------------------------------------------------------
__device__ __forceinline__ void mma_f16(float* d, const uint32_t* a,
                                        const uint32_t* b) {
    asm volatile(
        "mma.sync.aligned.m16n8k16.row.col.f32.f16.f16.f32 "
        "{%0,%1,%2,%3}, {%4,%5,%6,%7}, {%8,%9}, {%0,%1,%2,%3};"
        : "+f"(d[0]), "+f"(d[1]), "+f"(d[2]), "+f"(d[3])
        : "r"(a[0]), "r"(a[1]), "r"(a[2]), "r"(a[3]), "r"(b[0]), "r"(b[1]));
}
__device__ __forceinline__ void ldsm4(uint32_t* r, uint32_t addr) {
    asm volatile("ldmatrix.sync.aligned.m8n8.x4.shared.b16 {%0,%1,%2,%3}, [%4];"
                 : "=r"(r[0]), "=r"(r[1]), "=r"(r[2]), "=r"(r[3]) : "r"(addr));
}
__device__ __forceinline__ uint32_t smem_u32(const void* p) {
    uint32_t a;
    asm("{ .reg .u64 t; cvta.to.shared.u64 t, %1; cvt.u32.u64 %0, t; }"
        : "=r"(a) : "l"(p));
    return a;
}
__device__ __forceinline__ void cp16(uint32_t dst, const void* src) {
    asm volatile("cp.async.cg.shared.global [%0], [%1], 16;"
                 :: "r"(dst), "l"(src));
}
__device__ __forceinline__ int ld_acq(const int* p) {
    int v;
    asm volatile("ld.acquire.gpu.global.b32 %0, [%1];" : "=r"(v) : "l"(p) : "memory");
    return v;
}
__device__ __forceinline__ void red_release(int* p) {
    asm volatile("red.release.gpu.global.add.s32 [%0], 1;" :: "l"(p) : "memory");
}

// smem layout (union of both paths); rec needs the most: 207,872 B
#define TB_AH   0
#define TB_AM   16384
#define TB_BH   32768
#define TB_BM   49152
#define TB_SIZE 65536
#define GS_BIAS (2 * TB_SIZE)            // gemm path total: 131,584 B
// rec path (float offsets)
#define SM_W0   0
#define SM_W1   16384
#define SM_W2   32768
#define SM_W3   49152
#define SM_RCB1 51712
#define SM_B2C  51840
#define SM_FLOATS 51968
#define SMF_BYTES (SM_FLOATS * 4)        // 207,872 B

// ---------------------------------------------------------------------------
// Fused kernel: blocks 0..47 = recurrent LIF consumers (5-6 samples each);
// blocks 48..547 = gemm producer tiles in t-major order with flag release.
// ---------------------------------------------------------------------------
__global__ void __launch_bounds__(256, 1) fused_kernel(
    const float* __restrict__ x,    const float* __restrict__ b1,
    const float* __restrict__ rcW1, const float* __restrict__ rcb1,
    const float* __restrict__ W2,   const float* __restrict__ b2,
    const float* __restrict__ rcW2, const float* __restrict__ rcb2,
    const float* __restrict__ W3,   const float* __restrict__ b3,
    float* __restrict__ out)
{
    extern __shared__ char smg[];
    const int tid  = threadIdx.x;
    const int wid  = tid >> 5;
    const int lane = tid & 31;

    if (blockIdx.x >= REC_CTAS) {
        // =============== GEMM PRODUCER PATH ===============
        const uint32_t sbase = smem_u32(smg);
        const int g     = blockIdx.x - REC_CTAS;   // 0..499
        const int tcur  = g >> 1;                  // timestep this tile produces
        const int halfT = g & 1;                   // batch half
        const int mw    = wid & 1;
        const int nw    = wid >> 1;

        if (tid < 128) ((float*)(smg + GS_BIAS))[tid] = b1[tid];

        float acc[4][4][4];
        #pragma unroll
        for (int i = 0; i < 4; i++)
            #pragma unroll
            for (int j = 0; j < 4; j++)
                #pragma unroll
                for (int c = 0; c < 4; c++) acc[i][j][c] = 0.f;

        const int arow = tid >> 1;                 // local batch row 0..127
        const int akh  = tid & 1;
        const float* xrow = x + ((size_t)(halfT * 128 + arow) * Tsz + tcur) * DIN;
        const uint32_t aswz = (uint32_t)((arow & 7) << 4);
        const uint32_t abase = (uint32_t)(arow * 128);

        const int ra = (lane & 7) + ((lane >> 3) & 1) * 8;
        const int ka = (lane >> 4) * 8;
        const int rb = (lane & 7) + (lane >> 4) * 8;
        const int kbl = ((lane >> 3) & 1) * 8;
        const uint32_t lswz = (uint32_t)((lane & 7) << 4);

        int bn[4], bkc[4];
        uint32_t bdst[4];
        #pragma unroll
        for (int u = 0; u < 4; u++) {
            int c = tid + u * 256;
            bn[u]  = c >> 3;
            bkc[u] = c & 7;
            bdst[u] = (uint32_t)(bn[u] * 128)
                    + (((uint32_t)(bkc[u] * 16)) ^ ((uint32_t)((bn[u] & 7) << 4)));
        }

        float4 va[8];

        auto ldA = [&](int kt) {
            #pragma unroll
            for (int i = 0; i < 4; i++) {
                int kl = akh * 32 + i * 8;
                int gk = kt * KT + kl;
                va[i*2+0] = (gk <= DIN - 4) ? *(const float4*)(xrow + gk)
                                            : make_float4(0.f, 0.f, 0.f, 0.f);
                va[i*2+1] = (gk + 4 <= DIN - 4) ? *(const float4*)(xrow + gk + 4)
                                                : make_float4(0.f, 0.f, 0.f, 0.f);
            }
        };
        auto cpB = [&](int kt, uint32_t buf) {
            #pragma unroll
            for (int u = 0; u < 4; u++) {
                int src = kt * (128 * KT) + bn[u] * KT + bkc[u] * 8;
                cp16(buf + TB_BH + bdst[u], g_Bh + src);
                cp16(buf + TB_BM + bdst[u], g_Bm + src);
            }
            asm volatile("cp.async.commit_group;" ::: "memory");
        };
        auto stsA = [&](char* bufp) {
            #pragma unroll
            for (int i = 0; i < 4; i++) {
                int kl = akh * 32 + i * 8;
                float a[8];
                a[0]=va[i*2].x; a[1]=va[i*2].y; a[2]=va[i*2].z; a[3]=va[i*2].w;
                a[4]=va[i*2+1].x; a[5]=va[i*2+1].y; a[6]=va[i*2+1].z; a[7]=va[i*2+1].w;
                uint32_t hw[4], mw4[4];
                #pragma unroll
                for (int p = 0; p < 4; p++) {
                    __half2 h2 = __float22half2_rn(make_float2(a[2*p], a[2*p+1]));
                    float2 hf = __half22float2(h2);
                    __half2 m2 = __float22half2_rn(
                        make_float2(a[2*p] - hf.x, a[2*p+1] - hf.y));
                    hw[p]  = *reinterpret_cast<uint32_t*>(&h2);
                    mw4[p] = *reinterpret_cast<uint32_t*>(&m2);
                }
                uint32_t soff = abase + (((uint32_t)(kl * 2)) ^ aswz);
                *(uint4*)(bufp + TB_AH + soff) = make_uint4(hw[0],hw[1],hw[2],hw[3]);
                *(uint4*)(bufp + TB_AM + soff) = make_uint4(mw4[0],mw4[1],mw4[2],mw4[3]);
            }
        };

        ldA(0);
        cpB(0, sbase);
        stsA(smg);
        asm volatile("cp.async.wait_group 0;" ::: "memory");
        __syncthreads();

        for (int kt = 0; kt < NKT; kt++) {
            const uint32_t cbuf = (uint32_t)(kt & 1) * TB_SIZE;
            const uint32_t nbuf = (uint32_t)((kt + 1) & 1) * TB_SIZE;

            if (kt + 1 < NKT) {
                ldA(kt + 1);
                cpB(kt + 1, sbase + nbuf);
            }

            #pragma unroll
            for (int ks = 0; ks < 4; ks++) {
                const int kb = ks * 16;
                uint32_t ah[4][4], am[4][4], bh[4][2], bm[4][2];

                #pragma unroll
                for (int mt = 0; mt < 4; mt++) {
                    uint32_t row = (uint32_t)(mw * 64 + mt * 16 + ra);
                    uint32_t off = row * 128 + (((uint32_t)((kb + ka) * 2)) ^ lswz);
                    ldsm4(ah[mt], sbase + cbuf + TB_AH + off);
                    ldsm4(am[mt], sbase + cbuf + TB_AM + off);
                }
                #pragma unroll
                for (int g2 = 0; g2 < 2; g2++) {
                    uint32_t row = (uint32_t)(nw * 32 + g2 * 16 + rb);
                    uint32_t off = row * 128 + (((uint32_t)((kb + kbl) * 2)) ^ lswz);
                    uint32_t r4[4];
                    ldsm4(r4, sbase + cbuf + TB_BH + off);
                    bh[g2*2][0] = r4[0]; bh[g2*2][1] = r4[1];
                    bh[g2*2+1][0] = r4[2]; bh[g2*2+1][1] = r4[3];
                    ldsm4(r4, sbase + cbuf + TB_BM + off);
                    bm[g2*2][0] = r4[0]; bm[g2*2][1] = r4[1];
                    bm[g2*2+1][0] = r4[2]; bm[g2*2+1][1] = r4[3];
                }

                #pragma unroll
                for (int mt = 0; mt < 4; mt++)
                    #pragma unroll
                    for (int nt = 0; nt < 4; nt++) {
                        mma_f16(acc[mt][nt], am[mt], bh[nt]);   // mh
                        mma_f16(acc[mt][nt], ah[mt], bm[nt]);   // hm
                    }
                #pragma unroll
                for (int mt = 0; mt < 4; mt++)
                    #pragma unroll
                    for (int nt = 0; nt < 4; nt++)
                        mma_f16(acc[mt][nt], ah[mt], bh[nt]);   // hh
            }

            if (kt + 1 < NKT) {
                stsA(smg + nbuf);
                asm volatile("cp.async.wait_group 0;" ::: "memory");
                __syncthreads();
            }
        }

        // epilogue: h1[tcur][halfT*128 + r][c]
        const float* sb1 = (const float*)(smg + GS_BIAS);
        const int r_lo = lane >> 2;
        const int c_lo = (lane & 3) * 2;
        float* tbase = g_h1 + (size_t)tcur * (Bsz * Hd) + (size_t)(halfT * 128) * Hd;
        #pragma unroll
        for (int mt = 0; mt < 4; mt++) {
            #pragma unroll
            for (int hh8 = 0; hh8 < 2; hh8++) {
                int r = mw * 64 + mt * 16 + r_lo + hh8 * 8;
                float* orow = tbase + (size_t)r * Hd;
                #pragma unroll
                for (int nt = 0; nt < 4; nt++) {
                    int c = nw * 32 + nt * 8 + c_lo;
                    float2 v;
                    v.x = acc[mt][nt][hh8 * 2 + 0] + sb1[c];
                    v.y = acc[mt][nt][hh8 * 2 + 1] + sb1[c + 1];
                    *(float2*)(orow + c) = v;
                }
            }
        }

        // publish: this tile's half of timestep tcur is complete
        __threadfence();
        __syncthreads();
        if (tid == 0) red_release(&g_flag[tcur]);
        return;
    }

    // =============== RECURRENT CONSUMER PATH ===============
    float* sm    = (float*)smg;
    float* sW0   = sm + SM_W0;
    float* sW1   = sm + SM_W1;
    float* sW2   = sm + SM_W2;
    float* sW3   = sm + SM_W3;
    float* srcb1 = sm + SM_RCB1;
    float* sb2c  = sm + SM_B2C;

    {
        const float4* a = (const float4*)rcW1;
        const float4* c = (const float4*)W2;
        const float4* d = (const float4*)rcW2;
        float4* o0 = (float4*)sW0; float4* o1 = (float4*)sW1; float4* o2 = (float4*)sW2;
        for (int i = tid; i < (Hd * Hd) / 4; i += 256) {
            o0[i] = a[i]; o1[i] = c[i]; o2[i] = d[i];
        }
    }
    for (int i = tid; i < Hd * DOUT; i += 256) sW3[i] = W3[i];
    if (tid < Hd) {
        srcb1[tid] = rcb1[tid];
        sb2c[tid]  = b2[tid] + rcb2[tid];
    }
    __syncthreads();

    // variable samples per CTA: CTA i handles [i*256/48, (i+1)*256/48)
    const int s_start = (blockIdx.x * Bsz) / REC_CTAS;
    const int s_end   = ((blockIdx.x + 1) * Bsz) / REC_CTAS;
    const int cnt     = s_end - s_start;           // 5 or 6
    if (wid >= cnt) return;                        // extra warps exit

    const int b  = s_start + wid;                  // one sample per warp
    const int j0 = lane * 4;

    const float4 rcb1_r = *(const float4*)(srcb1 + j0);
    const float4 b2c_r  = *(const float4*)(sb2c + j0);

    float4 v1 = make_float4(0.f, 0.f, 0.f, 0.f);
    float4 v2 = make_float4(0.f, 0.f, 0.f, 0.f);
    float  acc = 0.f;
    unsigned m1[4] = {0u,0u,0u,0u};
    unsigned m2[4] = {0u,0u,0u,0u};

    const float* h1p = g_h1 + b * Hd + j0;

    const float* sW0j = sW0 + j0;
    const float* sW1j = sW1 + j0;
    const float* sW2j = sW2 + j0;

    // flag prefetch ring: fr[k&3] holds g_flag[k] for k = t+1 at step t
    int fr[4];
    #pragma unroll
    for (int k = 1; k <= 4; k++) fr[k & 3] = ld_acq(&g_flag[k]);

    // gate t = 0
    while (ld_acq(&g_flag[0]) < 2) __nanosleep(64);
    float4 h1v = *(const float4*)h1p;

    for (int t = 0; t < Tsz; t++) {
        // ---- phase 1: u = h1 + rcb1 + y1_old @ rcW1 ----
        float4 u;
        u.x = h1v.x + rcb1_r.x; u.y = h1v.y + rcb1_r.y;
        u.z = h1v.z + rcb1_r.z; u.w = h1v.w + rcb1_r.w;
        #pragma unroll
        for (int c = 0; c < 4; c++) {
            unsigned mm = m1[c];
            while (mm) {
                int bit = __ffs(mm) - 1; mm &= mm - 1u;
                float4 w = *(const float4*)(sW0j + ((bit << 2) | c) * Hd);
                u.x += w.x; u.y += w.y; u.z += w.z; u.w += w.w;
            }
        }
        v1.x += (u.x - v1.x) * 0.5f;  v1.y += (u.y - v1.y) * 0.5f;
        v1.z += (u.z - v1.z) * 0.5f;  v1.w += (u.w - v1.w) * 0.5f;
        bool s0 = v1.x >= 1.f, s1b = v1.y >= 1.f, s2b = v1.z >= 1.f, s3 = v1.w >= 1.f;
        if (s0) v1.x = 0.f;  if (s1b) v1.y = 0.f;
        if (s2b) v1.z = 0.f; if (s3) v1.w = 0.f;
        m1[0] = __ballot_sync(0xffffffffu, s0);
        m1[1] = __ballot_sync(0xffffffffu, s1b);
        m1[2] = __ballot_sync(0xffffffffu, s2b);
        m1[3] = __ballot_sync(0xffffffffu, s3);

        // ---- gate + prefetch h1 for t+1 (overlaps phase 2) ----
        float4 h1n = make_float4(0.f, 0.f, 0.f, 0.f);
        if (t + 1 < Tsz) {
            int f = fr[(t + 1) & 3];
            if (f < 2) {
                while ((f = ld_acq(&g_flag[t + 1])) < 2) __nanosleep(64);
            }
            h1n = *(const float4*)(h1p + (size_t)(t + 1) * (Bsz * Hd));
            if (t + 5 < Tsz) fr[(t + 1) & 3] = ld_acq(&g_flag[t + 5]);
        }

        // ---- phase 2: u2 = b2 + rcb2 + y1_new @ W2 + y2_old @ rcW2 ----
        float4 u2 = make_float4(b2c_r.x, b2c_r.y, b2c_r.z, b2c_r.w);
        #pragma unroll
        for (int c = 0; c < 4; c++) {
            unsigned mm = m1[c];
            while (mm) {
                int bit = __ffs(mm) - 1; mm &= mm - 1u;
                float4 w = *(const float4*)(sW1j + ((bit << 2) | c) * Hd);
                u2.x += w.x; u2.y += w.y; u2.z += w.z; u2.w += w.w;
            }
        }
        #pragma unroll
        for (int c = 0; c < 4; c++) {
            unsigned mm = m2[c];
            while (mm) {
                int bit = __ffs(mm) - 1; mm &= mm - 1u;
                float4 w = *(const float4*)(sW2j + ((bit << 2) | c) * Hd);
                u2.x += w.x; u2.y += w.y; u2.z += w.z; u2.w += w.w;
            }
        }
        v2.x += (u2.x - v2.x) * 0.5f;  v2.y += (u2.y - v2.y) * 0.5f;
        v2.z += (u2.z - v2.z) * 0.5f;  v2.w += (u2.w - v2.w) * 0.5f;
        s0 = v2.x >= 1.f; s1b = v2.y >= 1.f; s2b = v2.z >= 1.f; s3 = v2.w >= 1.f;
        if (s0) v2.x = 0.f;  if (s1b) v2.y = 0.f;
        if (s2b) v2.z = 0.f; if (s3) v2.w = 0.f;
        m2[0] = __ballot_sync(0xffffffffu, s0);
        m2[1] = __ballot_sync(0xffffffffu, s1b);
        m2[2] = __ballot_sync(0xffffffffu, s2b);
        m2[3] = __ballot_sync(0xffffffffu, s3);

        // ---- readout: acc += y2_new @ W3 ----
        if (lane < DOUT) {
            float a = 0.f;
            #pragma unroll
            for (int c = 0; c < 4; c++) {
                unsigned mm = m2[c];
                while (mm) {
                    int bit = __ffs(mm) - 1; mm &= mm - 1u;
                    a += sW3[((bit << 2) | c) * DOUT + lane];
                }
            }
            acc += a;
        }
        h1v = h1n;
    }

    if (lane < DOUT)
        out[b * DOUT + lane] = acc + (float)Tsz * b3[lane];
}

// ---------------------------------------------------------------------------
// Launch
// ---------------------------------------------------------------------------
extern "C" void kernel_launch(void* const* d_in, const int* in_sizes, int n_in,
                              void* d_out, int out_size)
{
    const float* x    = (const float*)d_in[0];
    const float* W1   = (const float*)d_in[1];
    const float* b1   = (const float*)d_in[2];
    const float* rcW1 = (const float*)d_in[3];
    const float* rcb1 = (const float*)d_in[4];
    const float* W2   = (const float*)d_in[5];
    const float* b2   = (const float*)d_in[6];
    const float* rcW2 = (const float*)d_in[7];
    const float* rcb2 = (const float*)d_in[8];
    const float* W3   = (const float*)d_in[9];
    const float* b3   = (const float*)d_in[10];
    float* out = (float*)d_out;

    cudaFuncSetAttribute(fused_kernel,
                         cudaFuncAttributeMaxDynamicSharedMemorySize, SMF_BYTES);

    // 0) fp16 split of W1 + zero the timestep flags (every replay)
    prep_kernel<<<(NKT * 128 * KT + 255) / 256, 256>>>(W1);

    // 1) fused producer/consumer: 48 rec CTAs + 500 t-major gemm tiles
    fused_kernel<<<REC_CTAS + GEMM_TILES, 256, SMF_BYTES>>>(
        x, b1, rcW1, rcb1, W2, b2, rcW2, rcb2, W3, b3, out);
}

// round 13
// speedup vs baseline: 1.0525x; 1.0525x over previous
#include <cuda_runtime.h>
#include <cuda_bf16.h>
#include <cuda_fp16.h>
#include <cstdint>

// Problem constants
#define Bsz   256
#define Tsz   250
#define DIN   700
#define Hd    128
#define DOUT  20
#define KT    64            // k-tile
#define NKT   11            // 704 / 64

#define REC_CTAS 40         // 6-7 samples per CTA (one warp per sample)
#define GEMM_TILES (Tsz * 2)
#define FSTRIDE 32          // flag stride in ints (128B -> one cache line per t)

// Scratch
__device__ float g_h1[Tsz * Bsz * Hd];                 // h1_all[t][b][h]
__device__ __half g_Bh[NKT * 128 * KT];                 // W1^T fp16 splits [kt][n][kk]
__device__ __half g_Bm[NKT * 128 * KT];
__device__ int    g_flag[Tsz * FSTRIDE];                // per-t arrivals (2 = ready), 128B apart

// ---------------------------------------------------------------------------
// Prep: fp16 two-term split of W1 -> g_B{h,m}[kt][n][kk]; zero g_flag.
// ---------------------------------------------------------------------------
__global__ void prep_kernel(const float* __restrict__ W1)
{
    int idx = blockIdx.x * blockDim.x + threadIdx.x;
    if (idx < Tsz * FSTRIDE) g_flag[idx] = 0;
    if (idx >= NKT * 128 * KT) return;
    int kt = idx / (128 * KT);
    int r  = idx - kt * (128 * KT);
    int n  = r >> 6;
    int kk = r & 63;
    int k  = kt * KT + kk;
    float w = (k < DIN) ? W1[k * Hd + n] : 0.f;
    __half h = __float2half_rn(w);
    float  rm = w - __half2float(h);
    g_Bh[idx] = h;
    g_Bm[idx] = __float2half_rn(rm);
}

// ---------------------------------------------------------------------------
// helpers
// ---------------------------------------------------------------------------
__device__ __forceinline__ void mma_f16(float* d, const uint32_t* a,
                                        const uint32_t* b) {
    asm volatile(
        "mma.sync.aligned.m16n8k16.row.col.f32.f16.f16.f32 "
        "{%0,%1,%2,%3}, {%4,%5,%6,%7}, {%8,%9}, {%0,%1,%2,%3};"
        : "+f"(d[0]), "+f"(d[1]), "+f"(d[2]), "+f"(d[3])
        : "r"(a[0]), "r"(a[1]), "r"(a[2]), "r"(a[3]), "r"(b[0]), "r"(b[1]));
}
__device__ __forceinline__ void ldsm4(uint32_t* r, uint32_t addr) {
    asm volatile("ldmatrix.sync.aligned.m8n8.x4.shared.b16 {%0,%1,%2,%3}, [%4];"
                 : "=r"(r[0]), "=r"(r[1]), "=r"(r[2]), "=r"(r[3]) : "r"(addr));
}
__device__ __forceinline__ uint32_t smem_u32(const void* p) {
    uint32_t a;
    asm("{ .reg .u64 t; cvta.to.shared.u64 t, %1; cvt.u32.u64 %0, t; }"
        : "=r"(a) : "l"(p));
    return a;
}
__device__ __forceinline__ void cp16(uint32_t dst, const void* src) {
    asm volatile("cp.async.cg.shared.global [%0], [%1], 16;"
                 :: "r"(dst), "l"(src));
}
__device__ __forceinline__ int ld_acq(const int* p) {
    int v;
    asm volatile("ld.acquire.gpu.global.b32 %0, [%1];" : "=r"(v) : "l"(p) : "memory");
    return v;
}
__device__ __forceinline__ void red_release(int* p) {
    asm volatile("red.release.gpu.global.add.s32 [%0], 1;" :: "l"(p) : "memory");
}
// wait until flag[t] == 2 with exponential backoff (contention-safe)
__device__ __forceinline__ void wait_flag(const int* p) {
    int back = 64;
    while (ld_acq(p) < 2) {
        __nanosleep(back);
        back = (back < 512) ? (back << 1) : 512;
    }
}

// smem layout (union of both paths); rec needs the most: 207,872 B
#define TB_AH   0
#define TB_AM   16384
#define TB_BH   32768
#define TB_BM   49152
#define TB_SIZE 65536
#define GS_BIAS (2 * TB_SIZE)            // gemm path total: 131,584 B
// rec path (float offsets)
#define SM_W0   0
#define SM_W1   16384
#define SM_W2   32768
#define SM_W3   49152
#define SM_RCB1 51712
#define SM_B2C  51840
#define SM_FLOATS 51968
#define SMF_BYTES (SM_FLOATS * 4)        // 207,872 B

// ---------------------------------------------------------------------------
// Fused kernel: blocks 0..39 = recurrent LIF consumers (6-7 samples each);
// blocks 40..539 = gemm producer tiles in t-major order with flag release.
// ---------------------------------------------------------------------------
__global__ void __launch_bounds__(256, 1) fused_kernel(
    const float* __restrict__ x,    const float* __restrict__ b1,
    const float* __restrict__ rcW1, const float* __restrict__ rcb1,
    const float* __restrict__ W2,   const float* __restrict__ b2,
    const float* __restrict__ rcW2, const float* __restrict__ rcb2,
    const float* __restrict__ W3,   const float* __restrict__ b3,
    float* __restrict__ out)
{
    extern __shared__ char smg[];
    const int tid  = threadIdx.x;
    const int wid  = tid >> 5;
    const int lane = tid & 31;

    if (blockIdx.x >= REC_CTAS) {
        // =============== GEMM PRODUCER PATH ===============
        const uint32_t sbase = smem_u32(smg);
        const int g     = blockIdx.x - REC_CTAS;   // 0..499
        const int tcur  = g >> 1;                  // timestep this tile produces
        const int halfT = g & 1;                   // batch half
        const int mw    = wid & 1;
        const int nw    = wid >> 1;

        if (tid < 128) ((float*)(smg + GS_BIAS))[tid] = b1[tid];

        float acc[4][4][4];
        #pragma unroll
        for (int i = 0; i < 4; i++)
            #pragma unroll
            for (int j = 0; j < 4; j++)
                #pragma unroll
                for (int c = 0; c < 4; c++) acc[i][j][c] = 0.f;

        const int arow = tid >> 1;                 // local batch row 0..127
        const int akh  = tid & 1;
        const float* xrow = x + ((size_t)(halfT * 128 + arow) * Tsz + tcur) * DIN;
        const uint32_t aswz = (uint32_t)((arow & 7) << 4);
        const uint32_t abase = (uint32_t)(arow * 128);

        const int ra = (lane & 7) + ((lane >> 3) & 1) * 8;
        const int ka = (lane >> 4) * 8;
        const int rb = (lane & 7) + (lane >> 4) * 8;
        const int kbl = ((lane >> 3) & 1) * 8;
        const uint32_t lswz = (uint32_t)((lane & 7) << 4);

        int bn[4], bkc[4];
        uint32_t bdst[4];
        #pragma unroll
        for (int u = 0; u < 4; u++) {
            int c = tid + u * 256;
            bn[u]  = c >> 3;
            bkc[u] = c & 7;
            bdst[u] = (uint32_t)(bn[u] * 128)
                    + (((uint32_t)(bkc[u] * 16)) ^ ((uint32_t)((bn[u] & 7) << 4)));
        }

        float4 va[8];

        auto ldA = [&](int kt) {
            #pragma unroll
            for (int i = 0; i < 4; i++) {
                int kl = akh * 32 + i * 8;
                int gk = kt * KT + kl;
                va[i*2+0] = (gk <= DIN - 4) ? *(const float4*)(xrow + gk)
                                            : make_float4(0.f, 0.f, 0.f, 0.f);
                va[i*2+1] = (gk + 4 <= DIN - 4) ? *(const float4*)(xrow + gk + 4)
                                                : make_float4(0.f, 0.f, 0.f, 0.f);
            }
        };
        auto cpB = [&](int kt, uint32_t buf) {
            #pragma unroll
            for (int u = 0; u < 4; u++) {
                int src = kt * (128 * KT) + bn[u] * KT + bkc[u] * 8;
                cp16(buf + TB_BH + bdst[u], g_Bh + src);
                cp16(buf + TB_BM + bdst[u], g_Bm + src);
            }
            asm volatile("cp.async.commit_group;" ::: "memory");
        };
        auto stsA = [&](char* bufp) {
            #pragma unroll
            for (int i = 0; i < 4; i++) {
                int kl = akh * 32 + i * 8;
                float a[8];
                a[0]=va[i*2].x; a[1]=va[i*2].y; a[2]=va[i*2].z; a[3]=va[i*2].w;
                a[4]=va[i*2+1].x; a[5]=va[i*2+1].y; a[6]=va[i*2+1].z; a[7]=va[i*2+1].w;
                uint32_t hw[4], mw4[4];
                #pragma unroll
                for (int p = 0; p < 4; p++) {
                    __half2 h2 = __float22half2_rn(make_float2(a[2*p], a[2*p+1]));
                    float2 hf = __half22float2(h2);
                    __half2 m2 = __float22half2_rn(
                        make_float2(a[2*p] - hf.x, a[2*p+1] - hf.y));
                    hw[p]  = *reinterpret_cast<uint32_t*>(&h2);
                    mw4[p] = *reinterpret_cast<uint32_t*>(&m2);
                }
                uint32_t soff = abase + (((uint32_t)(kl * 2)) ^ aswz);
                *(uint4*)(bufp + TB_AH + soff) = make_uint4(hw[0],hw[1],hw[2],hw[3]);
                *(uint4*)(bufp + TB_AM + soff) = make_uint4(mw4[0],mw4[1],mw4[2],mw4[3]);
            }
        };

        ldA(0);
        cpB(0, sbase);
        stsA(smg);
        asm volatile("cp.async.wait_group 0;" ::: "memory");
        __syncthreads();

        for (int kt = 0; kt < NKT; kt++) {
            const uint32_t cbuf = (uint32_t)(kt & 1) * TB_SIZE;
            const uint32_t nbuf = (uint32_t)((kt + 1) & 1) * TB_SIZE;

            if (kt + 1 < NKT) {
                ldA(kt + 1);
                cpB(kt + 1, sbase + nbuf);
            }

            #pragma unroll
            for (int ks = 0; ks < 4; ks++) {
                const int kb = ks * 16;
                uint32_t ah[4][4], am[4][4], bh[4][2], bm[4][2];

                #pragma unroll
                for (int mt = 0; mt < 4; mt++) {
                    uint32_t row = (uint32_t)(mw * 64 + mt * 16 + ra);
                    uint32_t off = row * 128 + (((uint32_t)((kb + ka) * 2)) ^ lswz);
                    ldsm4(ah[mt], sbase + cbuf + TB_AH + off);
                    ldsm4(am[mt], sbase + cbuf + TB_AM + off);
                }
                #pragma unroll
                for (int g2 = 0; g2 < 2; g2++) {
                    uint32_t row = (uint32_t)(nw * 32 + g2 * 16 + rb);
                    uint32_t off = row * 128 + (((uint32_t)((kb + kbl) * 2)) ^ lswz);
                    uint32_t r4[4];
                    ldsm4(r4, sbase + cbuf + TB_BH + off);
                    bh[g2*2][0] = r4[0]; bh[g2*2][1] = r4[1];
                    bh[g2*2+1][0] = r4[2]; bh[g2*2+1][1] = r4[3];
                    ldsm4(r4, sbase + cbuf + TB_BM + off);
                    bm[g2*2][0] = r4[0]; bm[g2*2][1] = r4[1];
                    bm[g2*2+1][0] = r4[2]; bm[g2*2+1][1] = r4[3];
                }

                #pragma unroll
                for (int mt = 0; mt < 4; mt++)
                    #pragma unroll
                    for (int nt = 0; nt < 4; nt++) {
                        mma_f16(acc[mt][nt], am[mt], bh[nt]);   // mh
                        mma_f16(acc[mt][nt], ah[mt], bm[nt]);   // hm
                    }
                #pragma unroll
                for (int mt = 0; mt < 4; mt++)
                    #pragma unroll
                    for (int nt = 0; nt < 4; nt++)
                        mma_f16(acc[mt][nt], ah[mt], bh[nt]);   // hh
            }

            if (kt + 1 < NKT) {
                stsA(smg + nbuf);
                asm volatile("cp.async.wait_group 0;" ::: "memory");
                __syncthreads();
            }
        }

        // epilogue: h1[tcur][halfT*128 + r][c]
        const float* sb1 = (const float*)(smg + GS_BIAS);
        const int r_lo = lane >> 2;
        const int c_lo = (lane & 3) * 2;
        float* tbase = g_h1 + (size_t)tcur * (Bsz * Hd) + (size_t)(halfT * 128) * Hd;
        #pragma unroll
        for (int mt = 0; mt < 4; mt++) {
            #pragma unroll
            for (int hh8 = 0; hh8 < 2; hh8++) {
                int r = mw * 64 + mt * 16 + r_lo + hh8 * 8;
                float* orow = tbase + (size_t)r * Hd;
                #pragma unroll
                for (int nt = 0; nt < 4; nt++) {
                    int c = nw * 32 + nt * 8 + c_lo;
                    float2 v;
                    v.x = acc[mt][nt][hh8 * 2 + 0] + sb1[c];
                    v.y = acc[mt][nt][hh8 * 2 + 1] + sb1[c + 1];
                    *(float2*)(orow + c) = v;
                }
            }
        }

        // publish: this tile's half of timestep tcur is complete
        __threadfence();
        __syncthreads();
        if (tid == 0) red_release(&g_flag[tcur * FSTRIDE]);
        return;
    }

    // =============== RECURRENT CONSUMER PATH ===============
    float* sm    = (float*)smg;
    float* sW0   = sm + SM_W0;
    float* sW1   = sm + SM_W1;
    float* sW2   = sm + SM_W2;
    float* sW3   = sm + SM_W3;
    float* srcb1 = sm + SM_RCB1;
    float* sb2c  = sm + SM_B2C;

    {
        const float4* a = (const float4*)rcW1;
        const float4* c = (const float4*)W2;
        const float4* d = (const float4*)rcW2;
        float4* o0 = (float4*)sW0; float4* o1 = (float4*)sW1; float4* o2 = (float4*)sW2;
        for (int i = tid; i < (Hd * Hd) / 4; i += 256) {
            o0[i] = a[i]; o1[i] = c[i]; o2[i] = d[i];
        }
    }
    for (int i = tid; i < Hd * DOUT; i += 256) sW3[i] = W3[i];
    if (tid < Hd) {
        srcb1[tid] = rcb1[tid];
        sb2c[tid]  = b2[tid] + rcb2[tid];
    }
    __syncthreads();

    // variable samples per CTA: CTA i handles [i*256/40, (i+1)*256/40)
    const int s_start = (blockIdx.x * Bsz) / REC_CTAS;
    const int s_end   = ((blockIdx.x + 1) * Bsz) / REC_CTAS;
    const int cnt     = s_end - s_start;           // 6 or 7
    if (wid >= cnt) return;                        // extra warps exit

    const int b  = s_start + wid;                  // one sample per warp
    const int j0 = lane * 4;

    const float4 rcb1_r = *(const float4*)(srcb1 + j0);
    const float4 b2c_r  = *(const float4*)(sb2c + j0);

    float4 v1 = make_float4(0.f, 0.f, 0.f, 0.f);
    float4 v2 = make_float4(0.f, 0.f, 0.f, 0.f);
    float  acc = 0.f;
    unsigned m1[4] = {0u,0u,0u,0u};
    unsigned m2[4] = {0u,0u,0u,0u};

    const float* h1p = g_h1 + b * Hd + j0;

    const float* sW0j = sW0 + j0;
    const float* sW1j = sW1 + j0;
    const float* sW2j = sW2 + j0;

    // flag prefetch ring: fr[k&3] holds g_flag[k] for k = t+1 at step t
    int fr[4];
    #pragma unroll
    for (int k = 1; k <= 4; k++) fr[k & 3] = ld_acq(&g_flag[k * FSTRIDE]);

    // gate t = 0 (backoff poll)
    wait_flag(&g_flag[0]);
    float4 h1v = *(const float4*)h1p;

    for (int t = 0; t < Tsz; t++) {
        // ---- phase 1: u = h1 + rcb1 + y1_old @ rcW1 ----
        float4 u;
        u.x = h1v.x + rcb1_r.x; u.y = h1v.y + rcb1_r.y;
        u.z = h1v.z + rcb1_r.z; u.w = h1v.w + rcb1_r.w;
        #pragma unroll
        for (int c = 0; c < 4; c++) {
            unsigned mm = m1[c];
            while (mm) {
                int bit = __ffs(mm) - 1; mm &= mm - 1u;
                float4 w = *(const float4*)(sW0j + ((bit << 2) | c) * Hd);
                u.x += w.x; u.y += w.y; u.z += w.z; u.w += w.w;
            }
        }
        v1.x += (u.x - v1.x) * 0.5f;  v1.y += (u.y - v1.y) * 0.5f;
        v1.z += (u.z - v1.z) * 0.5f;  v1.w += (u.w - v1.w) * 0.5f;
        bool s0 = v1.x >= 1.f, s1b = v1.y >= 1.f, s2b = v1.z >= 1.f, s3 = v1.w >= 1.f;
        if (s0) v1.x = 0.f;  if (s1b) v1.y = 0.f;
        if (s2b) v1.z = 0.f; if (s3) v1.w = 0.f;
        m1[0] = __ballot_sync(0xffffffffu, s0);
        m1[1] = __ballot_sync(0xffffffffu, s1b);
        m1[2] = __ballot_sync(0xffffffffu, s2b);
        m1[3] = __ballot_sync(0xffffffffu, s3);

        // ---- gate + prefetch h1 for t+1 (overlaps phase 2) ----
        float4 h1n = make_float4(0.f, 0.f, 0.f, 0.f);
        if (t + 1 < Tsz) {
            int f = fr[(t + 1) & 3];
            if (f < 2) wait_flag(&g_flag[(t + 1) * FSTRIDE]);
            h1n = *(const float4*)(h1p + (size_t)(t + 1) * (Bsz * Hd));
            if (t + 5 < Tsz) fr[(t + 1) & 3] = ld_acq(&g_flag[(t + 5) * FSTRIDE]);
        }

        // ---- phase 2: u2 = b2 + rcb2 + y1_new @ W2 + y2_old @ rcW2 ----
        float4 u2 = make_float4(b2c_r.x, b2c_r.y, b2c_r.z, b2c_r.w);
        #pragma unroll
        for (int c = 0; c < 4; c++) {
            unsigned mm = m1[c];
            while (mm) {
                int bit = __ffs(mm) - 1; mm &= mm - 1u;
                float4 w = *(const float4*)(sW1j + ((bit << 2) | c) * Hd);
                u2.x += w.x; u2.y += w.y; u2.z += w.z; u2.w += w.w;
            }
        }
        #pragma unroll
        for (int c = 0; c < 4; c++) {
            unsigned mm = m2[c];
            while (mm) {
                int bit = __ffs(mm) - 1; mm &= mm - 1u;
                float4 w = *(const float4*)(sW2j + ((bit << 2) | c) * Hd);
                u2.x += w.x; u2.y += w.y; u2.z += w.z; u2.w += w.w;
            }
        }
        v2.x += (u2.x - v2.x) * 0.5f;  v2.y += (u2.y - v2.y) * 0.5f;
        v2.z += (u2.z - v2.z) * 0.5f;  v2.w += (u2.w - v2.w) * 0.5f;
        s0 = v2.x >= 1.f; s1b = v2.y >= 1.f; s2b = v2.z >= 1.f; s3 = v2.w >= 1.f;
        if (s0) v2.x = 0.f;  if (s1b) v2.y = 0.f;
        if (s2b) v2.z = 0.f; if (s3) v2.w = 0.f;
        m2[0] = __ballot_sync(0xffffffffu, s0);
        m2[1] = __ballot_sync(0xffffffffu, s1b);
        m2[2] = __ballot_sync(0xffffffffu, s2b);
        m2[3] = __ballot_sync(0xffffffffu, s3);

        // ---- readout: acc += y2_new @ W3 ----
        if (lane < DOUT) {
            float a = 0.f;
            #pragma unroll
            for (int c = 0; c < 4; c++) {
                unsigned mm = m2[c];
                while (mm) {
                    int bit = __ffs(mm) - 1; mm &= mm - 1u;
                    a += sW3[((bit << 2) | c) * DOUT + lane];
                }
            }
            acc += a;
        }
        h1v = h1n;
    }

    if (lane < DOUT)
        out[b * DOUT + lane] = acc + (float)Tsz * b3[lane];
}

// ---------------------------------------------------------------------------
// Launch
// ---------------------------------------------------------------------------
extern "C" void kernel_launch(void* const* d_in, const int* in_sizes, int n_in,
                              void* d_out, int out_size)
{
    const float* x    = (const float*)d_in[0];
    const float* W1   = (const float*)d_in[1];
    const float* b1   = (const float*)d_in[2];
    const float* rcW1 = (const float*)d_in[3];
    const float* rcb1 = (const float*)d_in[4];
    const float* W2   = (const float*)d_in[5];
    const float* b2   = (const float*)d_in[6];
    const float* rcW2 = (const float*)d_in[7];
    const float* rcb2 = (const float*)d_in[8];
    const float* W3   = (const float*)d_in[9];
    const float* b3   = (const float*)d_in[10];
    float* out = (float*)d_out;

    cudaFuncSetAttribute(fused_kernel,
                         cudaFuncAttributeMaxDynamicSharedMemorySize, SMF_BYTES);

    // 0) fp16 split of W1 + zero the timestep flags (every replay)
    prep_kernel<<<(NKT * 128 * KT + 255) / 256, 256>>>(W1);

    // 1) fused producer/consumer: 40 rec CTAs + 500 t-major gemm tiles
    fused_kernel<<<REC_CTAS + GEMM_TILES, 256, SMF_BYTES>>>(
        x, b1, rcW1, rcb1, W2, b2, rcW2, rcb2, W3, b3, out);
}

// round 14
// speedup vs baseline: 1.2292x; 1.1679x over previous
#include <cuda_runtime.h>
#include <cuda_bf16.h>
#include <cuda_fp16.h>
#include <cstdint>

// Problem constants
#define Bsz   256
#define Tsz   250
#define DIN   700
#define Hd    128
#define DOUT  20
#define KT    64            // k-tile
#define NKT   11            // 704 / 64

#define REC_CTAS 44         // 5-6 samples per CTA (one warp per sample)
#define GEMM_TILES (Tsz * 2)
#define FSTRIDE 32          // flag stride in ints (128B per t)

// Scratch
__device__ float g_h1[Tsz * Bsz * Hd];                 // h1_all[t][b][h]
__device__ __half g_Bh[NKT * 128 * KT];                 // W1^T fp16 splits [kt][n][kk]
__device__ __half g_Bm[NKT * 128 * KT];
__device__ int    g_flag[Tsz * FSTRIDE];                // per-t arrivals (2 = ready)

// ---------------------------------------------------------------------------
// Prep: fp16 two-term split of W1 -> g_B{h,m}[kt][n][kk]; zero g_flag.
// ---------------------------------------------------------------------------
__global__ void prep_kernel(const float* __restrict__ W1)
{
    int idx = blockIdx.x * blockDim.x + threadIdx.x;
    if (idx < Tsz * FSTRIDE) g_flag[idx] = 0;
    if (idx >= NKT * 128 * KT) return;
    int kt = idx / (128 * KT);
    int r  = idx - kt * (128 * KT);
    int n  = r >> 6;
    int kk = r & 63;
    int k  = kt * KT + kk;
    float w = (k < DIN) ? W1[k * Hd + n] : 0.f;
    __half h = __float2half_rn(w);
    float  rm = w - __half2float(h);
    g_Bh[idx] = h;
    g_Bm[idx] = __float2half_rn(rm);
}

// ---------------------------------------------------------------------------
// helpers
// ---------------------------------------------------------------------------
__device__ __forceinline__ void mma_f16(float* d, const uint32_t* a,
                                        const uint32_t* b) {
    asm volatile(
        "mma.sync.aligned.m16n8k16.row.col.f32.f16.f16.f32 "
        "{%0,%1,%2,%3}, {%4,%5,%6,%7}, {%8,%9}, {%0,%1,%2,%3};"
        : "+f"(d[0]), "+f"(d[1]), "+f"(d[2]), "+f"(d[3])
        : "r"(a[0]), "r"(a[1]), "r"(a[2]), "r"(a[3]), "r"(b[0]), "r"(b[1]));
}
__device__ __forceinline__ void ldsm4(uint32_t* r, uint32_t addr) {
    asm volatile("ldmatrix.sync.aligned.m8n8.x4.shared.b16 {%0,%1,%2,%3}, [%4];"
                 : "=r"(r[0]), "=r"(r[1]), "=r"(r[2]), "=r"(r[3]) : "r"(addr));
}
__device__ __forceinline__ uint32_t smem_u32(const void* p) {
    uint32_t a;
    asm("{ .reg .u64 t; cvta.to.shared.u64 t, %1; cvt.u32.u64 %0, t; }"
        : "=r"(a) : "l"(p));
    return a;
}
__device__ __forceinline__ void cp16(uint32_t dst, const void* src) {
    asm volatile("cp.async.cg.shared.global [%0], [%1], 16;"
                 :: "r"(dst), "l"(src));
}
__device__ __forceinline__ int ld_acq(const int* p) {
    int v;
    asm volatile("ld.acquire.gpu.global.b32 %0, [%1];" : "=r"(v) : "l"(p) : "memory");
    return v;
}
__device__ __forceinline__ void red_release(int* p) {
    asm volatile("red.release.gpu.global.add.s32 [%0], 1;" :: "l"(p) : "memory");
}
__device__ __forceinline__ void wait_flag(const int* p) {
    int back = 64;
    while (ld_acq(p) < 2) {
        __nanosleep(back);
        back = (back < 512) ? (back << 1) : 512;
    }
}

// producer smem: two tile buffers of { AH 16K, AM 16K, BH 16K, BM 16K }
#define TB_AH   0
#define TB_AM   16384
#define TB_BH   32768
#define TB_BM   49152
#define TB_SIZE 65536
#define GS_BIAS (2 * TB_SIZE)            // producer total: 131,584 B
// consumer smem (float offsets)
#define SM_W0   0
#define SM_W1   16384
#define SM_W2   32768
#define SM_W3   49152
#define SM_RCB1 51712
#define SM_B2C  51840
#define SM_FLOATS 51968
#define SMF_BYTES (SM_FLOATS * 4)        // 207,872 B

// ---------------------------------------------------------------------------
// Fused kernel.
// blocks 0..REC_CTAS-1: recurrent LIF consumers.
// blocks REC_CTAS..: gemm producers, warp-specialized:
//   warps 0-3 = MMA (64x64 tile each, ratio-6 ldsm:MMA, no load work)
//   warps 4-7 = loaders (A: LDG+split+STS; B: cp.async), double-buffered.
// ---------------------------------------------------------------------------
__global__ void __launch_bounds__(256, 1) fused_kernel(
    const float* __restrict__ x,    const float* __restrict__ b1,
    const float* __restrict__ rcW1, const float* __restrict__ rcb1,
    const float* __restrict__ W2,   const float* __restrict__ b2,
    const float* __restrict__ rcW2, const float* __restrict__ rcb2,
    const float* __restrict__ W3,   const float* __restrict__ b3,
    float* __restrict__ out)
{
    extern __shared__ char smg[];
    const int tid  = threadIdx.x;
    const int wid  = tid >> 5;
    const int lane = tid & 31;

    if (blockIdx.x >= REC_CTAS) {
        // =============== GEMM PRODUCER PATH ===============
        const uint32_t sbase = smem_u32(smg);
        const int g     = blockIdx.x - REC_CTAS;   // 0..499
        const int tcur  = g >> 1;
        const int halfT = g & 1;

        if (tid < 128) ((float*)(smg + GS_BIAS))[tid] = b1[tid];

        if (wid >= 4) {
            // ---------------- LOADER WARPS (4-7) ----------------
            const int lt = tid - 128;              // 0..127, one A row each
            const float* xrow = x + ((size_t)(halfT * 128 + lt) * Tsz + tcur) * DIN;
            const uint32_t aswz  = (uint32_t)((lt & 7) << 4);
            const uint32_t abase = (uint32_t)(lt * 128);

            // B chunk mapping: 8 chunks of 16B per split per thread
            int bn[8], bkc[8];
            uint32_t bdst[8];
            #pragma unroll
            for (int u = 0; u < 8; u++) {
                int c = lt + u * 128;
                bn[u]  = c >> 3;
                bkc[u] = c & 7;
                bdst[u] = (uint32_t)(bn[u] * 128)
                        + (((uint32_t)(bkc[u] * 16)) ^ ((uint32_t)((bn[u] & 7) << 4)));
            }

            auto fill = [&](int kt, uint32_t buf, char* bufp) {
                // B via cp.async (fire first, overlap with A work)
                #pragma unroll
                for (int u = 0; u < 8; u++) {
                    int src = kt * (128 * KT) + bn[u] * KT + bkc[u] * 8;
                    cp16(buf + TB_BH + bdst[u], g_Bh + src);
                    cp16(buf + TB_BM + bdst[u], g_Bm + src);
                }
                asm volatile("cp.async.commit_group;" ::: "memory");
                // A: 64 floats of this row, split to h/m halves
                #pragma unroll
                for (int i = 0; i < 8; i++) {
                    int kl = i * 8;
                    int gk = kt * KT + kl;
                    float4 v0 = (gk <= DIN - 4) ? *(const float4*)(xrow + gk)
                                                : make_float4(0.f, 0.f, 0.f, 0.f);
                    float4 v1 = (gk + 4 <= DIN - 4) ? *(const float4*)(xrow + gk + 4)
                                                    : make_float4(0.f, 0.f, 0.f, 0.f);
                    float a[8] = {v0.x, v0.y, v0.z, v0.w, v1.x, v1.y, v1.z, v1.w};
                    uint32_t hw[4], mw4[4];
                    #pragma unroll
                    for (int p = 0; p < 4; p++) {
                        __half2 h2 = __float22half2_rn(make_float2(a[2*p], a[2*p+1]));
                        float2 hf = __half22float2(h2);
                        __half2 m2 = __float22half2_rn(
                            make_float2(a[2*p] - hf.x, a[2*p+1] - hf.y));
                        hw[p]  = *reinterpret_cast<uint32_t*>(&h2);
                        mw4[p] = *reinterpret_cast<uint32_t*>(&m2);
                    }
                    uint32_t soff = abase + (((uint32_t)(kl * 2)) ^ aswz);
                    *(uint4*)(bufp + TB_AH + soff) = make_uint4(hw[0],hw[1],hw[2],hw[3]);
                    *(uint4*)(bufp + TB_AM + soff) = make_uint4(mw4[0],mw4[1],mw4[2],mw4[3]);
                }
                asm volatile("cp.async.wait_group 0;" ::: "memory");
            };

            fill(0, sbase, smg);
            __syncthreads();
            for (int kt = 0; kt < NKT; kt++) {
                if (kt + 1 < NKT) {
                    uint32_t nb = (uint32_t)((kt + 1) & 1) * TB_SIZE;
                    fill(kt + 1, sbase + nb, smg + nb);
                }
                __syncthreads();
            }
            // join epilogue barrier, then done
            __threadfence();
            __syncthreads();
            return;
        }

        // ---------------- MMA WARPS (0-3): 64x64 each ----------------
        const int mw = wid & 1;                    // row half (64 rows)
        const int nw = wid >> 1;                   // col half (64 cols)

        float acc[4][8][4];
        #pragma unroll
        for (int i = 0; i < 4; i++)
            #pragma unroll
            for (int j = 0; j < 8; j++)
                #pragma unroll
                for (int c = 0; c < 4; c++) acc[i][j][c] = 0.f;

        const int ra = (lane & 7) + ((lane >> 3) & 1) * 8;
        const int ka = (lane >> 4) * 8;
        const int rb = (lane & 7) + (lane >> 4) * 8;
        const int kbl = ((lane >> 3) & 1) * 8;
        const uint32_t lswz = (uint32_t)((lane & 7) << 4);

        __syncthreads();                           // buf0 ready
        for (int kt = 0; kt < NKT; kt++) {
            const uint32_t cbuf = (uint32_t)(kt & 1) * TB_SIZE;

            #pragma unroll
            for (int ks = 0; ks < 4; ks++) {
                const int kb = ks * 16;
                uint32_t ah[4][4], am[4][4], bh[8][2], bm[8][2];

                #pragma unroll
                for (int mt = 0; mt < 4; mt++) {
                    uint32_t row = (uint32_t)(mw * 64 + mt * 16 + ra);
                    uint32_t off = row * 128 + (((uint32_t)((kb + ka) * 2)) ^ lswz);
                    ldsm4(ah[mt], sbase + cbuf + TB_AH + off);
                    ldsm4(am[mt], sbase + cbuf + TB_AM + off);
                }
                #pragma unroll
                for (int gi = 0; gi < 4; gi++) {
                    uint32_t row = (uint32_t)(nw * 64 + gi * 16 + rb);
                    uint32_t off = row * 128 + (((uint32_t)((kb + kbl) * 2)) ^ lswz);
                    uint32_t r4[4];
                    ldsm4(r4, sbase + cbuf + TB_BH + off);
                    bh[gi*2][0] = r4[0]; bh[gi*2][1] = r4[1];
                    bh[gi*2+1][0] = r4[2]; bh[gi*2+1][1] = r4[3];
                    ldsm4(r4, sbase + cbuf + TB_BM + off);
                    bm[gi*2][0] = r4[0]; bm[gi*2][1] = r4[1];
                    bm[gi*2+1][0] = r4[2]; bm[gi*2+1][1] = r4[3];
                }

                #pragma unroll
                for (int mt = 0; mt < 4; mt++)
                    #pragma unroll
                    for (int nt = 0; nt < 8; nt++) {
                        mma_f16(acc[mt][nt], am[mt], bh[nt]);   // mh
                        mma_f16(acc[mt][nt], ah[mt], bm[nt]);   // hm
                    }
                #pragma unroll
                for (int mt = 0; mt < 4; mt++)
                    #pragma unroll
                    for (int nt = 0; nt < 8; nt++)
                        mma_f16(acc[mt][nt], ah[mt], bh[nt]);   // hh
            }
            __syncthreads();
        }

        // epilogue: h1[tcur][halfT*128 + r][c] + bias
        const float* sb1 = (const float*)(smg + GS_BIAS);
        const int r_lo = lane >> 2;
        const int c_lo = (lane & 3) * 2;
        float* tbase = g_h1 + (size_t)tcur * (Bsz * Hd) + (size_t)(halfT * 128) * Hd;
        #pragma unroll
        for (int mt = 0; mt < 4; mt++) {
            #pragma unroll
            for (int hh8 = 0; hh8 < 2; hh8++) {
                int r = mw * 64 + mt * 16 + r_lo + hh8 * 8;
                float* orow = tbase + (size_t)r * Hd;
                #pragma unroll
                for (int nt = 0; nt < 8; nt++) {
                    int c = nw * 64 + nt * 8 + c_lo;
                    float2 v;
                    v.x = acc[mt][nt][hh8 * 2 + 0] + sb1[c];
                    v.y = acc[mt][nt][hh8 * 2 + 1] + sb1[c + 1];
                    *(float2*)(orow + c) = v;
                }
            }
        }

        __threadfence();
        __syncthreads();
        if (tid == 0) red_release(&g_flag[tcur * FSTRIDE]);
        return;
    }

    // =============== RECURRENT CONSUMER PATH ===============
    float* sm    = (float*)smg;
    float* sW0   = sm + SM_W0;
    float* sW1   = sm + SM_W1;
    float* sW2   = sm + SM_W2;
    float* sW3   = sm + SM_W3;
    float* srcb1 = sm + SM_RCB1;
    float* sb2c  = sm + SM_B2C;

    {
        const float4* a = (const float4*)rcW1;
        const float4* c = (const float4*)W2;
        const float4* d = (const float4*)rcW2;
        float4* o0 = (float4*)sW0; float4* o1 = (float4*)sW1; float4* o2 = (float4*)sW2;
        for (int i = tid; i < (Hd * Hd) / 4; i += 256) {
            o0[i] = a[i]; o1[i] = c[i]; o2[i] = d[i];
        }
    }
    for (int i = tid; i < Hd * DOUT; i += 256) sW3[i] = W3[i];
    if (tid < Hd) {
        srcb1[tid] = rcb1[tid];
        sb2c[tid]  = b2[tid] + rcb2[tid];
    }
    __syncthreads();

    const int s_start = (blockIdx.x * Bsz) / REC_CTAS;
    const int s_end   = ((blockIdx.x + 1) * Bsz) / REC_CTAS;
    const int cnt     = s_end - s_start;           // 5 or 6
    if (wid >= cnt) return;

    const int b  = s_start + wid;
    const int j0 = lane * 4;

    const float4 rcb1_r = *(const float4*)(srcb1 + j0);
    const float4 b2c_r  = *(const float4*)(sb2c + j0);

    float4 v1 = make_float4(0.f, 0.f, 0.f, 0.f);
    float4 v2 = make_float4(0.f, 0.f, 0.f, 0.f);
    float  acc = 0.f;
    unsigned m1[4] = {0u,0u,0u,0u};
    unsigned m2[4] = {0u,0u,0u,0u};

    const float* h1p = g_h1 + b * Hd + j0;

    const float* sW0j = sW0 + j0;
    const float* sW1j = sW1 + j0;
    const float* sW2j = sW2 + j0;

    int fr[4];
    #pragma unroll
    for (int k = 1; k <= 4; k++) fr[k & 3] = ld_acq(&g_flag[k * FSTRIDE]);

    wait_flag(&g_flag[0]);
    float4 h1v = *(const float4*)h1p;

    for (int t = 0; t < Tsz; t++) {
        // ---- phase 1 ----
        float4 u;
        u.x = h1v.x + rcb1_r.x; u.y = h1v.y + rcb1_r.y;
        u.z = h1v.z + rcb1_r.z; u.w = h1v.w + rcb1_r.w;
        #pragma unroll
        for (int c = 0; c < 4; c++) {
            unsigned mm = m1[c];
            while (mm) {
                int bit = __ffs(mm) - 1; mm &= mm - 1u;
                float4 w = *(const float4*)(sW0j + ((bit << 2) | c) * Hd);
                u.x += w.x; u.y += w.y; u.z += w.z; u.w += w.w;
            }
        }
        v1.x += (u.x - v1.x) * 0.5f;  v1.y += (u.y - v1.y) * 0.5f;
        v1.z += (u.z - v1.z) * 0.5f;  v1.w += (u.w - v1.w) * 0.5f;
        bool s0 = v1.x >= 1.f, s1b = v1.y >= 1.f, s2b = v1.z >= 1.f, s3 = v1.w >= 1.f;
        if (s0) v1.x = 0.f;  if (s1b) v1.y = 0.f;
        if (s2b) v1.z = 0.f; if (s3) v1.w = 0.f;
        m1[0] = __ballot_sync(0xffffffffu, s0);
        m1[1] = __ballot_sync(0xffffffffu, s1b);
        m1[2] = __ballot_sync(0xffffffffu, s2b);
        m1[3] = __ballot_sync(0xffffffffu, s3);

        // ---- gate + prefetch h1[t+1] ----
        float4 h1n = make_float4(0.f, 0.f, 0.f, 0.f);
        if (t + 1 < Tsz) {
            int f = fr[(t + 1) & 3];
            if (f < 2) wait_flag(&g_flag[(t + 1) * FSTRIDE]);
            h1n = *(const float4*)(h1p + (size_t)(t + 1) * (Bsz * Hd));
            if (t + 5 < Tsz) fr[(t + 1) & 3] = ld_acq(&g_flag[(t + 5) * FSTRIDE]);
        }

        // ---- phase 2 ----
        float4 u2 = make_float4(b2c_r.x, b2c_r.y, b2c_r.z, b2c_r.w);
        #pragma unroll
        for (int c = 0; c < 4; c++) {
            unsigned mm = m1[c];
            while (mm) {
                int bit = __ffs(mm) - 1; mm &= mm - 1u;
                float4 w = *(const float4*)(sW1j + ((bit << 2) | c) * Hd);
                u2.x += w.x; u2.y += w.y; u2.z += w.z; u2.w += w.w;
            }
        }
        #pragma unroll
        for (int c = 0; c < 4; c++) {
            unsigned mm = m2[c];
            while (mm) {
                int bit = __ffs(mm) - 1; mm &= mm - 1u;
                float4 w = *(const float4*)(sW2j + ((bit << 2) | c) * Hd);
                u2.x += w.x; u2.y += w.y; u2.z += w.z; u2.w += w.w;
            }
        }
        v2.x += (u2.x - v2.x) * 0.5f;  v2.y += (u2.y - v2.y) * 0.5f;
        v2.z += (u2.z - v2.z) * 0.5f;  v2.w += (u2.w - v2.w) * 0.5f;
        s0 = v2.x >= 1.f; s1b = v2.y >= 1.f; s2b = v2.z >= 1.f; s3 = v2.w >= 1.f;
        if (s0) v2.x = 0.f;  if (s1b) v2.y = 0.f;
        if (s2b) v2.z = 0.f; if (s3) v2.w = 0.f;
        m2[0] = __ballot_sync(0xffffffffu, s0);
        m2[1] = __ballot_sync(0xffffffffu, s1b);
        m2[2] = __ballot_sync(0xffffffffu, s2b);
        m2[3] = __ballot_sync(0xffffffffu, s3);

        // ---- readout ----
        if (lane < DOUT) {
            float a = 0.f;
            #pragma unroll
            for (int c = 0; c < 4; c++) {
                unsigned mm = m2[c];
                while (mm) {
                    int bit = __ffs(mm) - 1; mm &= mm - 1u;
                    a += sW3[((bit << 2) | c) * DOUT + lane];
                }
            }
            acc += a;
        }
        h1v = h1n;
    }

    if (lane < DOUT)
        out[b * DOUT + lane] = acc + (float)Tsz * b3[lane];
}

// ---------------------------------------------------------------------------
// Launch
// ---------------------------------------------------------------------------
extern "C" void kernel_launch(void* const* d_in, const int* in_sizes, int n_in,
                              void* d_out, int out_size)
{
    const float* x    = (const float*)d_in[0];
    const float* W1   = (const float*)d_in[1];
    const float* b1   = (const float*)d_in[2];
    const float* rcW1 = (const float*)d_in[3];
    const float* rcb1 = (const float*)d_in[4];
    const float* W2   = (const float*)d_in[5];
    const float* b2   = (const float*)d_in[6];
    const float* rcW2 = (const float*)d_in[7];
    const float* rcb2 = (const float*)d_in[8];
    const float* W3   = (const float*)d_in[9];
    const float* b3   = (const float*)d_in[10];
    float* out = (float*)d_out;

    cudaFuncSetAttribute(fused_kernel,
                         cudaFuncAttributeMaxDynamicSharedMemorySize, SMF_BYTES);

    // 0) fp16 split of W1 + zero flags (every replay)
    prep_kernel<<<(NKT * 128 * KT + 255) / 256, 256>>>(W1);

    // 1) fused: 44 rec CTAs + 500 warp-specialized gemm tiles
    fused_kernel<<<REC_CTAS + GEMM_TILES, 256, SMF_BYTES>>>(
        x, b1, rcW1, rcb1, W2, b2, rcW2, rcb2, W3, b3, out);
}